// round 15
// baseline (speedup 1.0000x reference)
#include <cuda_runtime.h>
#include <math.h>
#include <cstdint>

#define NNODES 20000
#define NEDGES 640000
#define NSZ 128
#define ESZ 20
#define CUTF 5.0f
#define PIF 3.14159265358979f

// ---------------- device scratch (precomputed node-side gate payloads) ----
__device__ float g_dsv[NNODES * 384];   // nsv  . soSV   [node][3][128]
__device__ float g_sev[NNODES * 128];   // soEV          [node][128]
__device__ float g_cns[NNODES * 128];   // nss  . soNS   [node][128]

typedef unsigned long long u64;

// ---------------- helpers ----------------
__device__ __forceinline__ void fma2(u64& d, u64 a, u64 b) {
    asm("fma.rn.f32x2 %0, %1, %2, %0;" : "+l"(d) : "l"(a), "l"(b));
}
__device__ __forceinline__ u64 pack2(float x) {
    u64 r; asm("mov.b64 %0, {%1, %1};" : "=l"(r) : "f"(x)); return r;
}
__device__ __forceinline__ float2 unpack2(u64 a) {
    float2 f; asm("mov.b64 {%0, %1}, %2;" : "=f"(f.x), "=f"(f.y) : "l"(a));
    return f;
}
__device__ __forceinline__ float4 f4_mul(float4 a, float4 b) {
    return make_float4(a.x*b.x, a.y*b.y, a.z*b.z, a.w*b.w);
}
// xv * g + s * f
__device__ __forceinline__ float4 f4_msg(float4 xv, float4 g, float s, float4 f) {
    return make_float4(fmaf(xv.x, g.x, s*f.x), fmaf(xv.y, g.y, s*f.y),
                       fmaf(xv.z, g.z, s*f.z), fmaf(xv.w, g.w, s*f.w));
}
__device__ __forceinline__ void red4(float* p, float4 v) {
    asm volatile("red.global.add.v4.f32 [%0], {%1, %2, %3, %4};"
                 :: "l"(p), "f"(v.x), "f"(v.y), "f"(v.z), "f"(v.w) : "memory");
}

// ---------------------------------------------------------------------------
// Kernel 1: node MLP + fused gate payloads.
// NB=80 -> 250 blocks = single wave at 2 blk/SM (smem 112 KB).
// ---------------------------------------------------------------------------
#define NB 80

__global__ void __launch_bounds__(256, 2) node_mlp(
    const float4* __restrict__ nss4, const float4* __restrict__ nsv4,
    const float* __restrict__ W1, const float* __restrict__ b1,
    const float* __restrict__ W2, const float* __restrict__ b2,
    float4* __restrict__ out)
{
    extern __shared__ float sm[];
    float* sW = sm;                    // 8192 (k-half tile, 32 KB)
    float* sX = sm + 8192;             // NB*128 = 10240 (40 KB)
    float* sH = sX + NB * 128;         // 10240 (40 KB)

    const int tid = threadIdx.x;
    const int n0 = blockIdx.x * NB;

    // init-out fold (no bounds checks: 20000 % NB == 0)
    {
        const float4* nssb = nss4 + (size_t)n0 * 32;
        float4* outS = out + (size_t)n0 * 32;
        for (int i = tid; i < NB * 32; i += 256) outS[i] = nssb[i];
        const float4* nsvb = nsv4 + (size_t)n0 * 96;
        float4* outV = out + (size_t)NNODES * 32 + (size_t)n0 * 96;
        for (int i = tid; i < NB * 96; i += 256) outV[i] = nsvb[i];
    }

    for (int i = tid; i < NB * 32; i += 256)
        ((float4*)sX)[i] = nss4[(size_t)n0 * 32 + i];
    __syncthreads();

    const int tx = tid & 31, ty = tid >> 5;
    const int c0 = tx * 4;

    u64 acc[10][2];

    // phase 1: H = silu(X @ W1 + b1), two k-halves
    #pragma unroll
    for (int i = 0; i < 10; i++) { acc[i][0] = 0ull; acc[i][1] = 0ull; }
    for (int h = 0; h < 2; h++) {
        for (int i = tid; i < 2048; i += 256)
            ((float4*)sW)[i] = ((const float4*)W1)[h * 2048 + i];
        __syncthreads();
        #pragma unroll 4
        for (int k = 0; k < 64; k += 4) {
            const ulonglong2 w0 = *(const ulonglong2*)&sW[(k + 0) * 128 + c0];
            const ulonglong2 w1 = *(const ulonglong2*)&sW[(k + 1) * 128 + c0];
            const ulonglong2 w2 = *(const ulonglong2*)&sW[(k + 2) * 128 + c0];
            const ulonglong2 w3 = *(const ulonglong2*)&sW[(k + 3) * 128 + c0];
            #pragma unroll
            for (int i = 0; i < 10; i++) {
                const float4 xv = *(const float4*)&sX[(ty * 10 + i) * 128 + h * 64 + k];
                const u64 x0 = pack2(xv.x), x1 = pack2(xv.y);
                const u64 x2 = pack2(xv.z), x3 = pack2(xv.w);
                fma2(acc[i][0], x0, w0.x); fma2(acc[i][1], x0, w0.y);
                fma2(acc[i][0], x1, w1.x); fma2(acc[i][1], x1, w1.y);
                fma2(acc[i][0], x2, w2.x); fma2(acc[i][1], x2, w2.y);
                fma2(acc[i][0], x3, w3.x); fma2(acc[i][1], x3, w3.y);
            }
        }
        __syncthreads();
    }
    {
        const float4 bb = __ldg((const float4*)&b1[c0]);
        #pragma unroll
        for (int i = 0; i < 10; i++) {
            const float2 lo = unpack2(acc[i][0]);
            const float2 hi = unpack2(acc[i][1]);
            float4 h = make_float4(lo.x + bb.x, lo.y + bb.y, hi.x + bb.z, hi.y + bb.w);
            h.x = h.x / (1.f + __expf(-h.x));
            h.y = h.y / (1.f + __expf(-h.y));
            h.z = h.z / (1.f + __expf(-h.z));
            h.w = h.w / (1.f + __expf(-h.w));
            *(float4*)&sH[(ty * 10 + i) * 128 + c0] = h;
        }
    }
    __syncthreads();

    // phase 2: three output tiles, two k-halves each
    for (int t = 0; t < 3; t++) {
        #pragma unroll
        for (int i = 0; i < 10; i++) { acc[i][0] = 0ull; acc[i][1] = 0ull; }
        for (int h = 0; h < 2; h++) {
            for (int i = tid; i < 2048; i += 256) {
                int k = i >> 5, jj = i & 31;
                ((float4*)sW)[i] =
                    *(const float4*)&W2[(size_t)(h * 64 + k) * 384 + t * 128 + jj * 4];
            }
            __syncthreads();
            #pragma unroll 4
            for (int k = 0; k < 64; k += 4) {
                const ulonglong2 w0 = *(const ulonglong2*)&sW[(k + 0) * 128 + c0];
                const ulonglong2 w1 = *(const ulonglong2*)&sW[(k + 1) * 128 + c0];
                const ulonglong2 w2 = *(const ulonglong2*)&sW[(k + 2) * 128 + c0];
                const ulonglong2 w3 = *(const ulonglong2*)&sW[(k + 3) * 128 + c0];
                #pragma unroll
                for (int i = 0; i < 10; i++) {
                    const float4 xv = *(const float4*)&sH[(ty * 10 + i) * 128 + h * 64 + k];
                    const u64 x0 = pack2(xv.x), x1 = pack2(xv.y);
                    const u64 x2 = pack2(xv.z), x3 = pack2(xv.w);
                    fma2(acc[i][0], x0, w0.x); fma2(acc[i][1], x0, w0.y);
                    fma2(acc[i][0], x1, w1.x); fma2(acc[i][1], x1, w1.y);
                    fma2(acc[i][0], x2, w2.x); fma2(acc[i][1], x2, w2.y);
                    fma2(acc[i][0], x3, w3.x); fma2(acc[i][1], x3, w3.y);
                }
            }
            __syncthreads();
        }
        const float4 bb = __ldg((const float4*)&b2[t * 128 + c0]);
        #pragma unroll
        for (int i = 0; i < 10; i++) {
            const int ln = ty * 10 + i;
            const int n = n0 + ln;
            const float2 lo = unpack2(acc[i][0]);
            const float2 hi = unpack2(acc[i][1]);
            const float4 so = make_float4(lo.x + bb.x, lo.y + bb.y,
                                          hi.x + bb.z, hi.y + bb.w);
            if (t == 0) {
                #pragma unroll
                for (int d3 = 0; d3 < 3; d3++) {
                    const float4 xv =
                        __ldg((const float4*)((const float*)nsv4 +
                                              (size_t)n * 384 + d3 * 128 + c0));
                    *(float4*)&g_dsv[(size_t)n * 384 + d3 * 128 + c0] =
                        f4_mul(xv, so);
                }
            } else if (t == 1) {
                *(float4*)&g_sev[(size_t)n * 128 + c0] = so;
            } else {
                const float4 xs = *(const float4*)&sX[ln * 128 + c0];
                *(float4*)&g_cns[(size_t)n * 128 + c0] = f4_mul(xs, so);
            }
        }
    }
}

// ---------------------------------------------------------------------------
// Kernel 2: per-edge filter (f32x2, EPW=6, k-step-2 with float2 ES broadcast)
//           + fused-gate messages + RED scatter.
// Same structure as the round-10/14 winner; only EPW raised 4->6
// (W-smem traffic/edge x2/3) with reg cap 128 (4 blocks/SM).
// ---------------------------------------------------------------------------
#define EPW 6

__global__ void __launch_bounds__(128, 4) edge_kernel(
    const float* __restrict__ edge_state, const float* __restrict__ edge_vector,
    const float* __restrict__ edge_distance, const int* __restrict__ edges,
    const float* __restrict__ Wf, const float* __restrict__ bf,
    float* __restrict__ out)
{
    __shared__ __align__(16) float sWf[ESZ * 384];
    __shared__ __align__(16) float sbf[384];
    __shared__ __align__(16) float sES[4][EPW * ESZ];

    const int tid = threadIdx.x;
    for (int i = tid; i < ESZ * 384 / 4; i += 128)
        ((float4*)sWf)[i] = ((const float4*)Wf)[i];
    for (int i = tid; i < 96; i += 128)
        ((float4*)sbf)[i] = ((const float4*)bf)[i];
    __syncthreads();

    const int lane  = tid & 31;
    const int warp  = tid >> 5;
    const int gwarp = blockIdx.x * 4 + warp;
    const int nwarp = gridDim.x * 4;
    const int c0    = lane * 4;
    float* myES = sES[warp];

    float* __restrict__ outS = out;
    float* __restrict__ outV = out + (size_t)NNODES * NSZ;

    for (int e0 = gwarp * EPW; e0 < NEDGES; e0 += nwarp * EPW) {
        // stage EPW edges' edge_state (contiguous, coalesced; clamp tail)
        __syncwarp();
        if (lane < EPW * 5) {
            const int r = lane / 5, cq = lane % 5;
            const int es_e = min(e0 + r, NEDGES - 1);
            ((float4*)myES)[lane] =
                __ldg((const float4*)&edge_state[(size_t)es_e * ESZ] + cq);
        }
        __syncwarp();

        // filter GEMM: acc = bf + es @ Wf (packed f32x2, k-step 2)
        u64 acc[EPW][6];
        {
            const ulonglong2 tS = *(const ulonglong2*)&sbf[c0];
            const ulonglong2 tE = *(const ulonglong2*)&sbf[128 + c0];
            const ulonglong2 tN = *(const ulonglong2*)&sbf[256 + c0];
            #pragma unroll
            for (int e = 0; e < EPW; e++) {
                acc[e][0] = tS.x; acc[e][1] = tS.y;
                acc[e][2] = tE.x; acc[e][3] = tE.y;
                acc[e][4] = tN.x; acc[e][5] = tN.y;
            }
        }
        #pragma unroll
        for (int k = 0; k < ESZ; k += 2) {
            const ulonglong2 wS0 = *(const ulonglong2*)&sWf[k * 384 + c0];
            const ulonglong2 wE0 = *(const ulonglong2*)&sWf[k * 384 + 128 + c0];
            const ulonglong2 wN0 = *(const ulonglong2*)&sWf[k * 384 + 256 + c0];
            const ulonglong2 wS1 = *(const ulonglong2*)&sWf[(k + 1) * 384 + c0];
            const ulonglong2 wE1 = *(const ulonglong2*)&sWf[(k + 1) * 384 + 128 + c0];
            const ulonglong2 wN1 = *(const ulonglong2*)&sWf[(k + 1) * 384 + 256 + c0];
            #pragma unroll
            for (int e = 0; e < EPW; e++) {
                const float2 es = *(const float2*)&myES[e * ESZ + k];  // bcast LDS.64
                const u64 p0 = pack2(es.x), p1 = pack2(es.y);
                fma2(acc[e][0], p0, wS0.x); fma2(acc[e][1], p0, wS0.y);
                fma2(acc[e][2], p0, wE0.x); fma2(acc[e][3], p0, wE0.y);
                fma2(acc[e][4], p0, wN0.x); fma2(acc[e][5], p0, wN0.y);
                fma2(acc[e][0], p1, wS1.x); fma2(acc[e][1], p1, wS1.y);
                fma2(acc[e][2], p1, wE1.x); fma2(acc[e][3], p1, wE1.y);
                fma2(acc[e][4], p1, wN1.x); fma2(acc[e][5], p1, wN1.y);
            }
        }

        // per-edge fused-gate messages + scatter
        #pragma unroll
        for (int e = 0; e < EPW; e++) {
            const int ed  = e0 + e;
            if (ed >= NEDGES) break;
            const int src = __ldg(&edges[2 * ed]);
            const int dst = __ldg(&edges[2 * ed + 1]);

            const float d = __ldg(&edge_distance[ed]);
            const float cu = (d < CUTF)
                ? 0.5f * (__cosf(PIF * d * (1.0f / CUTF)) + 1.0f)
                : 0.0f;

            const float v0 = __ldg(&edge_vector[3 * ed]);
            const float v1 = __ldg(&edge_vector[3 * ed + 1]);
            const float v2 = __ldg(&edge_vector[3 * ed + 2]);
            const float nrm = sqrtf(v0 * v0 + v1 * v1 + v2 * v2);
            const float inv = 1.0f / fmaxf(nrm, 1e-12f);
            const float en0 = v0 * inv, en1 = v1 * inv, en2 = v2 * inv;

            float2 p0 = unpack2(acc[e][0]), p1 = unpack2(acc[e][1]);
            float2 p2 = unpack2(acc[e][2]), p3 = unpack2(acc[e][3]);
            float2 p4 = unpack2(acc[e][4]), p5 = unpack2(acc[e][5]);
            const float4 fSV = make_float4(p0.x*cu, p0.y*cu, p1.x*cu, p1.y*cu);
            const float4 fEV = make_float4(p2.x*cu, p2.y*cu, p3.x*cu, p3.y*cu);
            const float4 fNS = make_float4(p4.x*cu, p4.y*cu, p5.x*cu, p5.y*cu);

            // payload: 5 float4 rows (sev, cns, dsv x3)
            const float4 sev = __ldg((const float4*)&g_sev[(size_t)src * 128 + c0]);
            const float4 cns = __ldg((const float4*)&g_cns[(size_t)src * 128 + c0]);
            const float* dsv = &g_dsv[(size_t)src * 384];
            const float4 dv0 = __ldg((const float4*)&dsv[c0]);
            const float4 dv1 = __ldg((const float4*)&dsv[128 + c0]);
            const float4 dv2 = __ldg((const float4*)&dsv[256 + c0]);

            const float4 tE = f4_mul(fEV, sev);   // fwEV . soEV (hoisted)

            // scalar message
            red4(&outS[(size_t)dst * NSZ + c0], f4_mul(fNS, cns));

            // vector messages
            float* ov = &outV[(size_t)dst * 384];
            red4(&ov[c0],       f4_msg(dv0, fSV, en0, tE));
            red4(&ov[128 + c0], f4_msg(dv1, fSV, en1, tE));
            red4(&ov[256 + c0], f4_msg(dv2, fSV, en2, tE));
        }
    }
}

// ---------------------------------------------------------------------------
extern "C" void kernel_launch(void* const* d_in, const int* in_sizes, int n_in,
                              void* d_out, int out_size)
{
    const float* nss           = (const float*)d_in[0];
    const float* nsv           = (const float*)d_in[1];
    const float* edge_state    = (const float*)d_in[2];
    const float* edge_vector   = (const float*)d_in[3];
    const float* edge_distance = (const float*)d_in[4];
    const int*   edges         = (const int*)d_in[5];
    const float* W_filter      = (const float*)d_in[6];
    const float* b_filter      = (const float*)d_in[7];
    const float* W1            = (const float*)d_in[8];
    const float* b1            = (const float*)d_in[9];
    const float* W2            = (const float*)d_in[10];
    const float* b2            = (const float*)d_in[11];
    float* out = (float*)d_out;

    const int smem1 = (8192 + 2 * NB * 128) * sizeof(float);   // 112 KB
    cudaFuncSetAttribute(node_mlp, cudaFuncAttributeMaxDynamicSharedMemorySize, smem1);
    node_mlp<<<NNODES / NB, 256, smem1>>>(
        (const float4*)nss, (const float4*)nsv, W1, b1, W2, b2, (float4*)out);

    edge_kernel<<<1480, 128>>>(edge_state, edge_vector, edge_distance,
                               edges, W_filter, b_filter, out);
}

// round 16
// speedup vs baseline: 1.1646x; 1.1646x over previous
#include <cuda_runtime.h>
#include <math.h>
#include <cstdint>

#define NNODES 20000
#define NEDGES 640000
#define NSZ 128
#define ESZ 20
#define CUTF 5.0f
#define PIF 3.14159265358979f

// ---------------- device scratch (precomputed node-side gate payloads) ----
__device__ float g_dsv[NNODES * 384];   // nsv  . soSV   [node][3][128]
__device__ float g_sev[NNODES * 128];   // soEV          [node][128]
__device__ float g_cns[NNODES * 128];   // nss  . soNS   [node][128]

typedef unsigned long long u64;

// ---------------- helpers ----------------
__device__ __forceinline__ void fma2(u64& d, u64 a, u64 b) {
    asm("fma.rn.f32x2 %0, %1, %2, %0;" : "+l"(d) : "l"(a), "l"(b));
}
__device__ __forceinline__ u64 pack2(float x) {
    u64 r; asm("mov.b64 %0, {%1, %1};" : "=l"(r) : "f"(x)); return r;
}
__device__ __forceinline__ float2 unpack2(u64 a) {
    float2 f; asm("mov.b64 {%0, %1}, %2;" : "=f"(f.x), "=f"(f.y) : "l"(a));
    return f;
}
__device__ __forceinline__ float4 f4_mul(float4 a, float4 b) {
    return make_float4(a.x*b.x, a.y*b.y, a.z*b.z, a.w*b.w);
}
// xv * g + s * f
__device__ __forceinline__ float4 f4_msg(float4 xv, float4 g, float s, float4 f) {
    return make_float4(fmaf(xv.x, g.x, s*f.x), fmaf(xv.y, g.y, s*f.y),
                       fmaf(xv.z, g.z, s*f.z), fmaf(xv.w, g.w, s*f.w));
}
__device__ __forceinline__ void red4(float* p, float4 v) {
    asm volatile("red.global.add.v4.f32 [%0], {%1, %2, %3, %4};"
                 :: "l"(p), "f"(v.x), "f"(v.y), "f"(v.z), "f"(v.w) : "memory");
}

// ---------------------------------------------------------------------------
// Kernel 1: node MLP + fused gate payloads. (round-14 winner, verbatim)
// NB=80 -> 250 blocks = single wave at 2 blk/SM (smem 112 KB).
// ---------------------------------------------------------------------------
#define NB 80

__global__ void __launch_bounds__(256, 2) node_mlp(
    const float4* __restrict__ nss4, const float4* __restrict__ nsv4,
    const float* __restrict__ W1, const float* __restrict__ b1,
    const float* __restrict__ W2, const float* __restrict__ b2,
    float4* __restrict__ out)
{
    extern __shared__ float sm[];
    float* sW = sm;                    // 8192 (k-half tile, 32 KB)
    float* sX = sm + 8192;             // NB*128 = 10240 (40 KB)
    float* sH = sX + NB * 128;         // 10240 (40 KB)

    const int tid = threadIdx.x;
    const int n0 = blockIdx.x * NB;

    // init-out fold (no bounds checks: 20000 % NB == 0)
    {
        const float4* nssb = nss4 + (size_t)n0 * 32;
        float4* outS = out + (size_t)n0 * 32;
        for (int i = tid; i < NB * 32; i += 256) outS[i] = nssb[i];
        const float4* nsvb = nsv4 + (size_t)n0 * 96;
        float4* outV = out + (size_t)NNODES * 32 + (size_t)n0 * 96;
        for (int i = tid; i < NB * 96; i += 256) outV[i] = nsvb[i];
    }

    for (int i = tid; i < NB * 32; i += 256)
        ((float4*)sX)[i] = nss4[(size_t)n0 * 32 + i];
    __syncthreads();

    const int tx = tid & 31, ty = tid >> 5;
    const int c0 = tx * 4;

    u64 acc[10][2];

    // phase 1: H = silu(X @ W1 + b1), two k-halves
    #pragma unroll
    for (int i = 0; i < 10; i++) { acc[i][0] = 0ull; acc[i][1] = 0ull; }
    for (int h = 0; h < 2; h++) {
        for (int i = tid; i < 2048; i += 256)
            ((float4*)sW)[i] = ((const float4*)W1)[h * 2048 + i];
        __syncthreads();
        #pragma unroll 4
        for (int k = 0; k < 64; k += 4) {
            const ulonglong2 w0 = *(const ulonglong2*)&sW[(k + 0) * 128 + c0];
            const ulonglong2 w1 = *(const ulonglong2*)&sW[(k + 1) * 128 + c0];
            const ulonglong2 w2 = *(const ulonglong2*)&sW[(k + 2) * 128 + c0];
            const ulonglong2 w3 = *(const ulonglong2*)&sW[(k + 3) * 128 + c0];
            #pragma unroll
            for (int i = 0; i < 10; i++) {
                const float4 xv = *(const float4*)&sX[(ty * 10 + i) * 128 + h * 64 + k];
                const u64 x0 = pack2(xv.x), x1 = pack2(xv.y);
                const u64 x2 = pack2(xv.z), x3 = pack2(xv.w);
                fma2(acc[i][0], x0, w0.x); fma2(acc[i][1], x0, w0.y);
                fma2(acc[i][0], x1, w1.x); fma2(acc[i][1], x1, w1.y);
                fma2(acc[i][0], x2, w2.x); fma2(acc[i][1], x2, w2.y);
                fma2(acc[i][0], x3, w3.x); fma2(acc[i][1], x3, w3.y);
            }
        }
        __syncthreads();
    }
    {
        const float4 bb = __ldg((const float4*)&b1[c0]);
        #pragma unroll
        for (int i = 0; i < 10; i++) {
            const float2 lo = unpack2(acc[i][0]);
            const float2 hi = unpack2(acc[i][1]);
            float4 h = make_float4(lo.x + bb.x, lo.y + bb.y, hi.x + bb.z, hi.y + bb.w);
            h.x = h.x / (1.f + __expf(-h.x));
            h.y = h.y / (1.f + __expf(-h.y));
            h.z = h.z / (1.f + __expf(-h.z));
            h.w = h.w / (1.f + __expf(-h.w));
            *(float4*)&sH[(ty * 10 + i) * 128 + c0] = h;
        }
    }
    __syncthreads();

    // phase 2: three output tiles, two k-halves each
    for (int t = 0; t < 3; t++) {
        #pragma unroll
        for (int i = 0; i < 10; i++) { acc[i][0] = 0ull; acc[i][1] = 0ull; }
        for (int h = 0; h < 2; h++) {
            for (int i = tid; i < 2048; i += 256) {
                int k = i >> 5, jj = i & 31;
                ((float4*)sW)[i] =
                    *(const float4*)&W2[(size_t)(h * 64 + k) * 384 + t * 128 + jj * 4];
            }
            __syncthreads();
            #pragma unroll 4
            for (int k = 0; k < 64; k += 4) {
                const ulonglong2 w0 = *(const ulonglong2*)&sW[(k + 0) * 128 + c0];
                const ulonglong2 w1 = *(const ulonglong2*)&sW[(k + 1) * 128 + c0];
                const ulonglong2 w2 = *(const ulonglong2*)&sW[(k + 2) * 128 + c0];
                const ulonglong2 w3 = *(const ulonglong2*)&sW[(k + 3) * 128 + c0];
                #pragma unroll
                for (int i = 0; i < 10; i++) {
                    const float4 xv = *(const float4*)&sH[(ty * 10 + i) * 128 + h * 64 + k];
                    const u64 x0 = pack2(xv.x), x1 = pack2(xv.y);
                    const u64 x2 = pack2(xv.z), x3 = pack2(xv.w);
                    fma2(acc[i][0], x0, w0.x); fma2(acc[i][1], x0, w0.y);
                    fma2(acc[i][0], x1, w1.x); fma2(acc[i][1], x1, w1.y);
                    fma2(acc[i][0], x2, w2.x); fma2(acc[i][1], x2, w2.y);
                    fma2(acc[i][0], x3, w3.x); fma2(acc[i][1], x3, w3.y);
                }
            }
            __syncthreads();
        }
        const float4 bb = __ldg((const float4*)&b2[t * 128 + c0]);
        #pragma unroll
        for (int i = 0; i < 10; i++) {
            const int ln = ty * 10 + i;
            const int n = n0 + ln;
            const float2 lo = unpack2(acc[i][0]);
            const float2 hi = unpack2(acc[i][1]);
            const float4 so = make_float4(lo.x + bb.x, lo.y + bb.y,
                                          hi.x + bb.z, hi.y + bb.w);
            if (t == 0) {
                #pragma unroll
                for (int d3 = 0; d3 < 3; d3++) {
                    const float4 xv =
                        __ldg((const float4*)((const float*)nsv4 +
                                              (size_t)n * 384 + d3 * 128 + c0));
                    *(float4*)&g_dsv[(size_t)n * 384 + d3 * 128 + c0] =
                        f4_mul(xv, so);
                }
            } else if (t == 1) {
                *(float4*)&g_sev[(size_t)n * 128 + c0] = so;
            } else {
                const float4 xs = *(const float4*)&sX[ln * 128 + c0];
                *(float4*)&g_cns[(size_t)n * 128 + c0] = f4_mul(xs, so);
            }
        }
    }
}

// ---------------------------------------------------------------------------
// Kernel 2: per-edge filter + fused-gate messages + RED scatter.
// EPW=4 structure of the round-14 winner, with fewer memory instructions:
//   - ES read as ONE LDS.128 per edge per k-quad (was 2 LDS.64)
//   - edges read as ONE LDG.64 (int2)
// ---------------------------------------------------------------------------
#define EPW 4

__global__ void __launch_bounds__(128, 5) edge_kernel(
    const float* __restrict__ edge_state, const float* __restrict__ edge_vector,
    const float* __restrict__ edge_distance, const int* __restrict__ edges,
    const float* __restrict__ Wf, const float* __restrict__ bf,
    float* __restrict__ out)
{
    __shared__ __align__(16) float sWf[ESZ * 384];
    __shared__ __align__(16) float sbf[384];
    __shared__ __align__(16) float sES[4][EPW * ESZ];

    const int tid = threadIdx.x;
    for (int i = tid; i < ESZ * 384 / 4; i += 128)
        ((float4*)sWf)[i] = ((const float4*)Wf)[i];
    for (int i = tid; i < 96; i += 128)
        ((float4*)sbf)[i] = ((const float4*)bf)[i];
    __syncthreads();

    const int lane  = tid & 31;
    const int warp  = tid >> 5;
    const int gwarp = blockIdx.x * 4 + warp;
    const int nwarp = gridDim.x * 4;
    const int c0    = lane * 4;
    float* myES = sES[warp];

    float* __restrict__ outS = out;
    float* __restrict__ outV = out + (size_t)NNODES * NSZ;

    for (int e0 = gwarp * EPW; e0 < NEDGES; e0 += nwarp * EPW) {
        // stage EPW edges' edge_state (contiguous, coalesced)
        __syncwarp();
        if (lane < EPW * 5) {
            ((float4*)myES)[lane] =
                __ldg((const float4*)&edge_state[(size_t)e0 * ESZ] + lane);
        }
        __syncwarp();

        // filter GEMM: acc = bf + es @ Wf (packed f32x2, k-quad loop)
        u64 acc[EPW][6];
        {
            const ulonglong2 tS = *(const ulonglong2*)&sbf[c0];
            const ulonglong2 tE = *(const ulonglong2*)&sbf[128 + c0];
            const ulonglong2 tN = *(const ulonglong2*)&sbf[256 + c0];
            #pragma unroll
            for (int e = 0; e < EPW; e++) {
                acc[e][0] = tS.x; acc[e][1] = tS.y;
                acc[e][2] = tE.x; acc[e][3] = tE.y;
                acc[e][4] = tN.x; acc[e][5] = tN.y;
            }
        }
        #pragma unroll
        for (int kq = 0; kq < ESZ; kq += 4) {
            // ES: one LDS.128 per edge covering k..k+3 (ESZ=20 -> 16B aligned)
            float4 es4[EPW];
            #pragma unroll
            for (int e = 0; e < EPW; e++)
                es4[e] = *(const float4*)&myES[e * ESZ + kq];

            // sub-step A: k = kq, kq+1
            {
                const ulonglong2 wS0 = *(const ulonglong2*)&sWf[kq * 384 + c0];
                const ulonglong2 wE0 = *(const ulonglong2*)&sWf[kq * 384 + 128 + c0];
                const ulonglong2 wN0 = *(const ulonglong2*)&sWf[kq * 384 + 256 + c0];
                const ulonglong2 wS1 = *(const ulonglong2*)&sWf[(kq + 1) * 384 + c0];
                const ulonglong2 wE1 = *(const ulonglong2*)&sWf[(kq + 1) * 384 + 128 + c0];
                const ulonglong2 wN1 = *(const ulonglong2*)&sWf[(kq + 1) * 384 + 256 + c0];
                #pragma unroll
                for (int e = 0; e < EPW; e++) {
                    const u64 p0 = pack2(es4[e].x), p1 = pack2(es4[e].y);
                    fma2(acc[e][0], p0, wS0.x); fma2(acc[e][1], p0, wS0.y);
                    fma2(acc[e][2], p0, wE0.x); fma2(acc[e][3], p0, wE0.y);
                    fma2(acc[e][4], p0, wN0.x); fma2(acc[e][5], p0, wN0.y);
                    fma2(acc[e][0], p1, wS1.x); fma2(acc[e][1], p1, wS1.y);
                    fma2(acc[e][2], p1, wE1.x); fma2(acc[e][3], p1, wE1.y);
                    fma2(acc[e][4], p1, wN1.x); fma2(acc[e][5], p1, wN1.y);
                }
            }
            // sub-step B: k = kq+2, kq+3
            {
                const ulonglong2 wS0 = *(const ulonglong2*)&sWf[(kq + 2) * 384 + c0];
                const ulonglong2 wE0 = *(const ulonglong2*)&sWf[(kq + 2) * 384 + 128 + c0];
                const ulonglong2 wN0 = *(const ulonglong2*)&sWf[(kq + 2) * 384 + 256 + c0];
                const ulonglong2 wS1 = *(const ulonglong2*)&sWf[(kq + 3) * 384 + c0];
                const ulonglong2 wE1 = *(const ulonglong2*)&sWf[(kq + 3) * 384 + 128 + c0];
                const ulonglong2 wN1 = *(const ulonglong2*)&sWf[(kq + 3) * 384 + 256 + c0];
                #pragma unroll
                for (int e = 0; e < EPW; e++) {
                    const u64 p0 = pack2(es4[e].z), p1 = pack2(es4[e].w);
                    fma2(acc[e][0], p0, wS0.x); fma2(acc[e][1], p0, wS0.y);
                    fma2(acc[e][2], p0, wE0.x); fma2(acc[e][3], p0, wE0.y);
                    fma2(acc[e][4], p0, wN0.x); fma2(acc[e][5], p0, wN0.y);
                    fma2(acc[e][0], p1, wS1.x); fma2(acc[e][1], p1, wS1.y);
                    fma2(acc[e][2], p1, wE1.x); fma2(acc[e][3], p1, wE1.y);
                    fma2(acc[e][4], p1, wN1.x); fma2(acc[e][5], p1, wN1.y);
                }
            }
        }

        // per-edge fused-gate messages + scatter
        #pragma unroll
        for (int e = 0; e < EPW; e++) {
            const int ed  = e0 + e;
            const int2 sd = __ldg((const int2*)&edges[2 * ed]);
            const int src = sd.x, dst = sd.y;

            const float d = __ldg(&edge_distance[ed]);
            const float cu = (d < CUTF)
                ? 0.5f * (__cosf(PIF * d * (1.0f / CUTF)) + 1.0f)
                : 0.0f;

            const float v0 = __ldg(&edge_vector[3 * ed]);
            const float v1 = __ldg(&edge_vector[3 * ed + 1]);
            const float v2 = __ldg(&edge_vector[3 * ed + 2]);
            const float nrm = sqrtf(v0 * v0 + v1 * v1 + v2 * v2);
            const float inv = 1.0f / fmaxf(nrm, 1e-12f);
            const float en0 = v0 * inv, en1 = v1 * inv, en2 = v2 * inv;

            float2 p0 = unpack2(acc[e][0]), p1 = unpack2(acc[e][1]);
            float2 p2 = unpack2(acc[e][2]), p3 = unpack2(acc[e][3]);
            float2 p4 = unpack2(acc[e][4]), p5 = unpack2(acc[e][5]);
            const float4 fSV = make_float4(p0.x*cu, p0.y*cu, p1.x*cu, p1.y*cu);
            const float4 fEV = make_float4(p2.x*cu, p2.y*cu, p3.x*cu, p3.y*cu);
            const float4 fNS = make_float4(p4.x*cu, p4.y*cu, p5.x*cu, p5.y*cu);

            // payload: 5 float4 rows (sev, cns, dsv x3)
            const float4 sev = __ldg((const float4*)&g_sev[(size_t)src * 128 + c0]);
            const float4 cns = __ldg((const float4*)&g_cns[(size_t)src * 128 + c0]);
            const float* dsv = &g_dsv[(size_t)src * 384];
            const float4 dv0 = __ldg((const float4*)&dsv[c0]);
            const float4 dv1 = __ldg((const float4*)&dsv[128 + c0]);
            const float4 dv2 = __ldg((const float4*)&dsv[256 + c0]);

            const float4 tE = f4_mul(fEV, sev);   // fwEV . soEV (hoisted)

            // scalar message
            red4(&outS[(size_t)dst * NSZ + c0], f4_mul(fNS, cns));

            // vector messages
            float* ov = &outV[(size_t)dst * 384];
            red4(&ov[c0],       f4_msg(dv0, fSV, en0, tE));
            red4(&ov[128 + c0], f4_msg(dv1, fSV, en1, tE));
            red4(&ov[256 + c0], f4_msg(dv2, fSV, en2, tE));
        }
    }
}

// ---------------------------------------------------------------------------
extern "C" void kernel_launch(void* const* d_in, const int* in_sizes, int n_in,
                              void* d_out, int out_size)
{
    const float* nss           = (const float*)d_in[0];
    const float* nsv           = (const float*)d_in[1];
    const float* edge_state    = (const float*)d_in[2];
    const float* edge_vector   = (const float*)d_in[3];
    const float* edge_distance = (const float*)d_in[4];
    const int*   edges         = (const int*)d_in[5];
    const float* W_filter      = (const float*)d_in[6];
    const float* b_filter      = (const float*)d_in[7];
    const float* W1            = (const float*)d_in[8];
    const float* b1            = (const float*)d_in[9];
    const float* W2            = (const float*)d_in[10];
    const float* b2            = (const float*)d_in[11];
    float* out = (float*)d_out;

    const int smem1 = (8192 + 2 * NB * 128) * sizeof(float);   // 112 KB
    cudaFuncSetAttribute(node_mlp, cudaFuncAttributeMaxDynamicSharedMemorySize, smem1);
    node_mlp<<<NNODES / NB, 256, smem1>>>(
        (const float4*)nss, (const float4*)nsv, W1, b1, W2, b2, (float4*)out);

    edge_kernel<<<1480, 128>>>(edge_state, edge_vector, edge_distance,
                               edges, W_filter, b_filter, out);
}